// round 1
// baseline (speedup 1.0000x reference)
#include <cuda_runtime.h>
#include <math.h>

// ---------------------------------------------------------------------------
// Problem constants
// ---------------------------------------------------------------------------
#define TT   256
#define PP   256
#define EE   300
#define HH   256
#define NPOS 65536            // T*P
#define G4   1024             // 4H
#define D2H  512              // 2H
#define NC   4608             // 9 * 512 feature columns
#define MM   50000
#define CC   16384

// ---------------------------------------------------------------------------
// Device scratch (static allocations only)
// ---------------------------------------------------------------------------
__device__ float    g_GxF[(size_t)NPOS * G4];        // 268 MB
__device__ float    g_GxB[(size_t)NPOS * G4];        // 268 MB
__device__ float    g_flat[(size_t)NPOS * D2H];      // 134 MB  [hf | hb]
__device__ float    g_Bcat[(size_t)D2H * NC];        // 9.4 MB
__device__ float    g_Feat[(size_t)NPOS * NC];       // 1.21 GB
__device__ float    g_cstate[2 * PP * HH];           // 512 KB
__device__ unsigned g_pairKeys[(size_t)3 * CC * D2H];// 100 MB
__device__ unsigned g_triKeys[(size_t)CC * D2H];     // 33 MB
__device__ float    g_pv[(size_t)3 * CC * D2H];      // 100 MB
__device__ float    g_tv[(size_t)CC * D2H];          // 33 MB
__device__ float    g_feats[(size_t)CC * 2048];      // 134 MB
__device__ float    g_final[(size_t)CC * D2H];       // 33 MB

// ---------------------------------------------------------------------------
// Helpers
// ---------------------------------------------------------------------------
__device__ __forceinline__ float sigmoidf_(float x) { return 1.0f / (1.0f + expf(-x)); }

// monotonic float->uint map for atomicMax pooling
__device__ __forceinline__ unsigned fmap(float f) {
    unsigned b = __float_as_uint(f);
    return (b & 0x80000000u) ? ~b : (b | 0x80000000u);
}
__device__ __forceinline__ float funmap(unsigned u) {
    return (u & 0x80000000u) ? __uint_as_float(u & 0x7FFFFFFFu)
                             : __uint_as_float(~u);
}

__device__ __forceinline__ float warpReduceSum(float v) {
    #pragma unroll
    for (int o = 16; o > 0; o >>= 1) v += __shfl_down_sync(0xffffffffu, v, o);
    return v;
}
__device__ __forceinline__ float blockReduceSum256(float v) {
    __shared__ float sh[8];
    int lane = threadIdx.x & 31, wid = threadIdx.x >> 5;
    v = warpReduceSum(v);
    if (lane == 0) sh[wid] = v;
    __syncthreads();
    v = (threadIdx.x < 8) ? sh[threadIdx.x] : 0.0f;
    if (wid == 0) v = warpReduceSum(v);
    return v;   // valid in thread 0
}

// ---------------------------------------------------------------------------
// Pack Wcat [512, 4608]:
//  cols [512q, 512q+512): q=0..5 -> pair type k=q/2, half h=q%2 rows of pair_hW[k]
//                         q=6..8 -> tri_hW third (q-6)
// ---------------------------------------------------------------------------
__global__ void pack_bcat_kernel(const float* __restrict__ pair_hW,
                                 const float* __restrict__ tri_hW,
                                 float* __restrict__ Bcat) {
    const int total = D2H * NC;
    for (int idx = blockIdx.x * blockDim.x + threadIdx.x; idx < total;
         idx += gridDim.x * blockDim.x) {
        int d = idx / NC, col = idx % NC;
        int q = col >> 9, c = col & 511;
        float v;
        if (q < 6) {
            int k = q >> 1, h = q & 1;
            v = pair_hW[(size_t)k * (G4 * D2H) + (size_t)(h * 512 + d) * D2H + c];
        } else {
            v = tri_hW[(size_t)((q - 6) * 512 + d) * D2H + c];
        }
        Bcat[idx] = v;
    }
}

// ---------------------------------------------------------------------------
// Generic fp32 tiled GEMM. C[M,N] = A[M,K] @ op(B) + bias
//  TRANSB=false: B is [K,N] row-major (NN)
//  TRANSB=true : B is [N,K] row-major (NT, C = A @ B^T)
//  M % 128 == 0, N % 128 == 0, K % 4 == 0 (K tail handled by zero padding)
// ---------------------------------------------------------------------------
template <bool TRANSB>
__global__ __launch_bounds__(256)
void sgemm_kernel(const float* __restrict__ A, const float* __restrict__ B,
                  const float* __restrict__ bias, float* __restrict__ C,
                  int M, int N, int K) {
    __shared__ float As[8][132];
    __shared__ float Bs[8][132];

    const int tid = threadIdx.x;
    const int tx = tid & 15, ty = tid >> 4;
    const int row0 = blockIdx.y * 128 + ty * 8;
    const int col0 = blockIdx.x * 128 + tx * 8;

    float acc[8][8];
    #pragma unroll
    for (int i = 0; i < 8; ++i)
        #pragma unroll
        for (int j = 0; j < 8; ++j) acc[i][j] = 0.0f;

    const int nkt = (K + 7) / 8;
    // A load coords
    const int aRow = tid >> 1, aK4 = (tid & 1) * 4;
    // B load coords
    const int bRowNN = tid >> 5, bColNN = (tid & 31) * 4;   // NN
    const int bN = tid >> 1, bK4 = (tid & 1) * 4;           // NT

    for (int kt = 0; kt < nkt; ++kt) {
        const int kbase = kt * 8;
        // ---- load A tile (transposed into As[k][m]) ----
        {
            int k = kbase + aK4;
            float4 a = make_float4(0.f, 0.f, 0.f, 0.f);
            if (k < K)
                a = *(const float4*)&A[(size_t)(blockIdx.y * 128 + aRow) * K + k];
            As[aK4 + 0][aRow] = a.x;
            As[aK4 + 1][aRow] = a.y;
            As[aK4 + 2][aRow] = a.z;
            As[aK4 + 3][aRow] = a.w;
        }
        // ---- load B tile into Bs[k][n] ----
        if (!TRANSB) {
            int k = kbase + bRowNN;
            float4 b = make_float4(0.f, 0.f, 0.f, 0.f);
            if (k < K)
                b = *(const float4*)&B[(size_t)k * N + blockIdx.x * 128 + bColNN];
            *(float4*)&Bs[bRowNN][bColNN] = b;
        } else {
            int k = kbase + bK4;
            float4 b = make_float4(0.f, 0.f, 0.f, 0.f);
            if (k < K)
                b = *(const float4*)&B[(size_t)(blockIdx.x * 128 + bN) * K + k];
            Bs[bK4 + 0][bN] = b.x;
            Bs[bK4 + 1][bN] = b.y;
            Bs[bK4 + 2][bN] = b.z;
            Bs[bK4 + 3][bN] = b.w;
        }
        __syncthreads();

        #pragma unroll
        for (int kk = 0; kk < 8; ++kk) {
            float4 a0 = *(const float4*)&As[kk][ty * 8];
            float4 a1 = *(const float4*)&As[kk][ty * 8 + 4];
            float4 b0 = *(const float4*)&Bs[kk][tx * 8];
            float4 b1 = *(const float4*)&Bs[kk][tx * 8 + 4];
            float ar[8] = {a0.x, a0.y, a0.z, a0.w, a1.x, a1.y, a1.z, a1.w};
            float br[8] = {b0.x, b0.y, b0.z, b0.w, b1.x, b1.y, b1.z, b1.w};
            #pragma unroll
            for (int i = 0; i < 8; ++i)
                #pragma unroll
                for (int j = 0; j < 8; ++j)
                    acc[i][j] += ar[i] * br[j];
        }
        __syncthreads();
    }

    float bv[8];
    #pragma unroll
    for (int j = 0; j < 8; ++j) bv[j] = bias ? bias[col0 + j] : 0.0f;

    #pragma unroll
    for (int i = 0; i < 8; ++i) {
        float4 o0 = make_float4(acc[i][0] + bv[0], acc[i][1] + bv[1],
                                acc[i][2] + bv[2], acc[i][3] + bv[3]);
        float4 o1 = make_float4(acc[i][4] + bv[4], acc[i][5] + bv[5],
                                acc[i][6] + bv[6], acc[i][7] + bv[7]);
        *(float4*)&C[(size_t)(row0 + i) * N + col0] = o0;
        *(float4*)&C[(size_t)(row0 + i) * N + col0 + 4] = o1;
    }
}

// ---------------------------------------------------------------------------
// Zero the segment-max key arrays
// ---------------------------------------------------------------------------
__global__ void zero_keys_kernel(unsigned* __restrict__ pk, unsigned* __restrict__ tk) {
    const size_t np = (size_t)3 * CC * D2H;
    const size_t nt = (size_t)CC * D2H;
    for (size_t i = blockIdx.x * (size_t)blockDim.x + threadIdx.x; i < np + nt;
         i += (size_t)gridDim.x * blockDim.x) {
        if (i < np) pk[i] = 0u; else tk[i - np] = 0u;
    }
}

// ---------------------------------------------------------------------------
// One recurrent step, both directions. Fused GEMM (h @ whh^T) + gates.
// grid (8 pTiles, 8 jTiles, 2 dirs), 256 threads.
// Each thread: 4 p-rows x 1 j-col x 4 gates.
// h-history lives in g_flat; c-state private per (dir,p,j) thread -> no races.
// ---------------------------------------------------------------------------
__global__ __launch_bounds__(256)
void lstm_step_kernel(const float* __restrict__ GxF, const float* __restrict__ GxB,
                      const float* __restrict__ whhF, const float* __restrict__ whhB,
                      float* __restrict__ flat, float* __restrict__ cstate, int s) {
    const int dir = blockIdx.z;
    const int tcur = dir ? (TT - 1 - s) : s;
    const int p0 = blockIdx.x * 32;
    const int j0 = blockIdx.y * 32;
    const int tid = threadIdx.x, tx = tid & 31, tyy = tid >> 5;
    const float* Gx = dir ? GxB : GxF;
    const float* whh = dir ? whhB : whhF;
    const int hcol = dir * HH;
    const int nprevT = dir ? (tcur + 1) : (tcur - 1);

    __shared__ float Hs[32][36];       // [p][k]
    __shared__ float Ws[4][32][33];    // [gate][k][j]

    float acc[4][4];
    #pragma unroll
    for (int i = 0; i < 4; ++i)
        #pragma unroll
        for (int g = 0; g < 4; ++g) acc[i][g] = 0.0f;

    for (int kt = 0; kt < 8; ++kt) {
        const int k0 = kt * 32;
        // load H tile
        {
            int r = tid >> 3, c4 = (tid & 7) * 4;
            float4 v = make_float4(0.f, 0.f, 0.f, 0.f);
            if (s > 0)
                v = *(const float4*)&flat[(size_t)(nprevT * PP + p0 + r) * D2H + hcol + k0 + c4];
            *(float4*)&Hs[r][c4] = v;
        }
        // load W tiles for 4 gates: Ws[g][k][j]
        #pragma unroll
        for (int i = 0; i < 4; ++i) {
            int lin = tid + i * 256;
            int g = lin >> 8, rest = lin & 255;
            int j = rest >> 3, c4 = (rest & 7) * 4;
            float4 w = *(const float4*)&whh[(size_t)(g * HH + j0 + j) * HH + k0 + c4];
            Ws[g][c4 + 0][j] = w.x;
            Ws[g][c4 + 1][j] = w.y;
            Ws[g][c4 + 2][j] = w.z;
            Ws[g][c4 + 3][j] = w.w;
        }
        __syncthreads();
        #pragma unroll
        for (int kk = 0; kk < 32; ++kk) {
            float b0 = Ws[0][kk][tx], b1 = Ws[1][kk][tx];
            float b2 = Ws[2][kk][tx], b3 = Ws[3][kk][tx];
            #pragma unroll
            for (int i = 0; i < 4; ++i) {
                float a = Hs[tyy + 8 * i][kk];
                acc[i][0] += a * b0;
                acc[i][1] += a * b1;
                acc[i][2] += a * b2;
                acc[i][3] += a * b3;
            }
        }
        __syncthreads();
    }

    const int j = j0 + tx;
    #pragma unroll
    for (int i = 0; i < 4; ++i) {
        const int p = p0 + tyy + 8 * i;
        const size_t n = (size_t)tcur * PP + p;
        float gi = acc[i][0] + Gx[n * G4 + 0 * HH + j];
        float gf = acc[i][1] + Gx[n * G4 + 1 * HH + j];
        float gg = acc[i][2] + Gx[n * G4 + 2 * HH + j];
        float go = acc[i][3] + Gx[n * G4 + 3 * HH + j];
        const size_t ci = (size_t)dir * (PP * HH) + (size_t)p * HH + j;
        float c = (s == 0) ? 0.0f : cstate[ci];
        float cn = sigmoidf_(gf) * c + sigmoidf_(gi) * tanhf(gg);
        float h = sigmoidf_(go) * tanhf(cn);
        cstate[ci] = cn;
        flat[n * D2H + hcol + j] = h;
    }
}

// ---------------------------------------------------------------------------
// Pair occurrence scatter-max: rep = FeatA[occ1] + FeatB[occ2] (bias deferred)
// grid = 3*MM blocks, 512 threads (one column each)
// ---------------------------------------------------------------------------
__global__ void pair_scatter_kernel(const float* __restrict__ Feat,
                                    const int* __restrict__ occ1,
                                    const int* __restrict__ occ2,
                                    const int* __restrict__ seg,
                                    unsigned* __restrict__ keys) {
    const int b = blockIdx.x;
    const int k = b / MM, m = b % MM;
    const int o1 = occ1[k * MM + m];
    const int o2 = occ2[k * MM + m];
    const int sg = seg[k * MM + m];
    const float* f1 = Feat + (size_t)o1 * NC + (size_t)(2 * k) * 512;
    const float* f2 = Feat + (size_t)o2 * NC + (size_t)(2 * k + 1) * 512;
    unsigned* dst = keys + ((size_t)k * CC + sg) * D2H;
    const int c = threadIdx.x;
    float r = f1[c] + f2[c];
    atomicMax(&dst[c], fmap(r));
}

__global__ void tri_scatter_kernel(const float* __restrict__ Feat,
                                   const int* __restrict__ o1,
                                   const int* __restrict__ o2,
                                   const int* __restrict__ o3,
                                   const int* __restrict__ tseg,
                                   unsigned* __restrict__ keys) {
    const int m = blockIdx.x;
    const int a = o1[m], bb = o2[m], d = o3[m];
    const int sg = tseg[m];
    const float* f1 = Feat + (size_t)a * NC + 6 * 512;
    const float* f2 = Feat + (size_t)bb * NC + 7 * 512;
    const float* f3 = Feat + (size_t)d * NC + 8 * 512;
    unsigned* dst = keys + (size_t)sg * D2H;
    const int c = threadIdx.x;
    float r = f1[c] + f2[c] + f3[c];
    atomicMax(&dst[c], fmap(r));
}

// ---------------------------------------------------------------------------
// Pair finalize: pv = tanh(nonempty ? max+hb : backoff); pair_logits = pv.oW+ob
// grid = 3*CC blocks (b = k*CC + s), 256 threads, 2 columns each
// ---------------------------------------------------------------------------
__global__ __launch_bounds__(256)
void pair_final_kernel(const unsigned* __restrict__ keys,
                       const float* __restrict__ hb,
                       const float* __restrict__ backoff,
                       const float* __restrict__ oW,
                       const float* __restrict__ ob,
                       float* __restrict__ pv, float* __restrict__ out) {
    const int b = blockIdx.x;
    const int k = b >> 14;
    const unsigned* src = keys + (size_t)b * D2H;
    float partial = 0.0f;
    #pragma unroll
    for (int it = 0; it < 2; ++it) {
        int c = threadIdx.x + it * 256;
        unsigned u = src[c];
        float val = u ? (funmap(u) + hb[k * D2H + c]) : backoff[k * D2H + c];
        float t = tanhf(val);
        pv[(size_t)b * D2H + c] = t;
        partial += t * oW[k * D2H + c];
    }
    float tot = blockReduceSum256(partial);
    if (threadIdx.x == 0) out[CC + b] = tot + ob[k];
}

__global__ __launch_bounds__(256)
void tri_final_kernel(const unsigned* __restrict__ keys,
                      const float* __restrict__ hb,
                      const float* __restrict__ backoff,
                      float* __restrict__ tv) {
    const int s = blockIdx.x;
    const unsigned* src = keys + (size_t)s * D2H;
    #pragma unroll
    for (int it = 0; it < 2; ++it) {
        int c = threadIdx.x + it * 256;
        unsigned u = src[c];
        float val = u ? (funmap(u) + hb[c]) : backoff[c];
        tv[(size_t)s * D2H + c] = tanhf(val);
    }
}

// ---------------------------------------------------------------------------
// Gather final features: [pv2[idx0], pv1[idx1], pv0[idx2], tv[s]]
// ---------------------------------------------------------------------------
__global__ void gather_feats_kernel(const float* __restrict__ pv,
                                    const float* __restrict__ tv,
                                    const int* __restrict__ tpi,
                                    float* __restrict__ feats) {
    const int s = blockIdx.x;
    const int i0 = tpi[s * 3 + 0];
    const int i1 = tpi[s * 3 + 1];
    const int i2 = tpi[s * 3 + 2];
    for (int j = threadIdx.x; j < 2048; j += blockDim.x) {
        int q = j >> 9, c = j & 511;
        float v;
        if (q == 0)      v = pv[((size_t)2 * CC + i0) * D2H + c];
        else if (q == 1) v = pv[((size_t)1 * CC + i1) * D2H + c];
        else if (q == 2) v = pv[(size_t)i2 * D2H + c];
        else             v = tv[(size_t)s * D2H + c];
        feats[(size_t)s * 2048 + j] = v;
    }
}

// ---------------------------------------------------------------------------
// Triple logits: out[s] = relu(final[s]) . out_tW + out_tb
// ---------------------------------------------------------------------------
__global__ __launch_bounds__(256)
void triple_logit_kernel(const float* __restrict__ fin,
                         const float* __restrict__ tW,
                         const float* __restrict__ tb,
                         float* __restrict__ out) {
    const int s = blockIdx.x;
    float partial = 0.0f;
    #pragma unroll
    for (int it = 0; it < 2; ++it) {
        int c = threadIdx.x + it * 256;
        float v = fin[(size_t)s * D2H + c];
        v = v > 0.0f ? v : 0.0f;
        partial += v * tW[c];
    }
    float tot = blockReduceSum256(partial);
    if (threadIdx.x == 0) out[s] = tot + tb[0];
}

// ---------------------------------------------------------------------------
// Launcher
// ---------------------------------------------------------------------------
extern "C" void kernel_launch(void* const* d_in, const int* in_sizes, int n_in,
                              void* d_out, int out_size) {
    const float* x        = (const float*)d_in[0];
    const float* wih_f    = (const float*)d_in[1];
    const float* whh_f    = (const float*)d_in[2];
    const float* b_f      = (const float*)d_in[3];
    const float* wih_b    = (const float*)d_in[4];
    const float* whh_b    = (const float*)d_in[5];
    const float* b_b      = (const float*)d_in[6];
    const float* pair_hW  = (const float*)d_in[7];
    const float* pair_hb  = (const float*)d_in[8];
    const float* pair_oW  = (const float*)d_in[9];
    const float* pair_ob  = (const float*)d_in[10];
    const float* pair_bo  = (const float*)d_in[11];
    const float* tri_hW   = (const float*)d_in[12];
    const float* tri_hb   = (const float*)d_in[13];
    const float* tri_bo   = (const float*)d_in[14];
    const float* all_hW   = (const float*)d_in[15];
    const float* all_hb   = (const float*)d_in[16];
    const float* out_tW   = (const float*)d_in[17];
    const float* out_tb   = (const float*)d_in[18];
    const int*   occ1     = (const int*)d_in[19];
    const int*   occ2     = (const int*)d_in[20];
    const int*   seg      = (const int*)d_in[21];
    const int*   tri_o1   = (const int*)d_in[22];
    const int*   tri_o2   = (const int*)d_in[23];
    const int*   tri_o3   = (const int*)d_in[24];
    const int*   tri_seg  = (const int*)d_in[25];
    const int*   tri_pi   = (const int*)d_in[26];
    float* out = (float*)d_out;

    float *GxF, *GxB, *flat, *Bcat, *Feat, *cst, *pv, *tv, *feats, *fin;
    unsigned *pk, *tk;
    cudaGetSymbolAddress((void**)&GxF,  g_GxF);
    cudaGetSymbolAddress((void**)&GxB,  g_GxB);
    cudaGetSymbolAddress((void**)&flat, g_flat);
    cudaGetSymbolAddress((void**)&Bcat, g_Bcat);
    cudaGetSymbolAddress((void**)&Feat, g_Feat);
    cudaGetSymbolAddress((void**)&cst,  g_cstate);
    cudaGetSymbolAddress((void**)&pk,   g_pairKeys);
    cudaGetSymbolAddress((void**)&tk,   g_triKeys);
    cudaGetSymbolAddress((void**)&pv,   g_pv);
    cudaGetSymbolAddress((void**)&tv,   g_tv);
    cudaGetSymbolAddress((void**)&feats,g_feats);
    cudaGetSymbolAddress((void**)&fin,  g_final);

    // 1) pack feature weight matrix
    pack_bcat_kernel<<<2304, 256>>>(pair_hW, tri_hW, Bcat);

    // 2) input projections (NT gemm, bias folded)
    sgemm_kernel<true><<<dim3(G4 / 128, NPOS / 128), 256>>>(x, wih_f, b_f, GxF, NPOS, G4, EE);
    sgemm_kernel<true><<<dim3(G4 / 128, NPOS / 128), 256>>>(x, wih_b, b_b, GxB, NPOS, G4, EE);

    // 3) zero segment-max keys (runs while recurrence proceeds in-stream)
    zero_keys_kernel<<<32768, 256>>>(pk, tk);

    // 4) BiLSTM recurrence, 256 fused steps (both directions per launch)
    for (int s = 0; s < TT; ++s)
        lstm_step_kernel<<<dim3(PP / 32, HH / 32, 2), 256>>>(GxF, GxB, whh_f, whh_b, flat, cst, s);

    // 5) dense feature transform for all positions (NN gemm, no bias)
    sgemm_kernel<false><<<dim3(NC / 128, NPOS / 128), 256>>>(flat, Bcat, nullptr, Feat, NPOS, NC, D2H);

    // 6) segment max pooling via atomicMax
    pair_scatter_kernel<<<3 * MM, 512>>>(Feat, occ1, occ2, seg, pk);
    tri_scatter_kernel<<<MM, 512>>>(Feat, tri_o1, tri_o2, tri_o3, tri_seg, tk);

    // 7) finalize pooled vectors (+ pair logits)
    pair_final_kernel<<<3 * CC, 256>>>(pk, pair_hb, pair_bo, pair_oW, pair_ob, pv, out);
    tri_final_kernel<<<CC, 256>>>(tk, tri_hb, tri_bo, tv);

    // 8) gather 8H features, final MLP, triple logits
    gather_feats_kernel<<<CC, 256>>>(pv, tv, tri_pi, feats);
    sgemm_kernel<false><<<dim3(D2H / 128, CC / 128), 256>>>(feats, all_hW, all_hb, fin, CC, D2H, 2048);
    triple_logit_kernel<<<CC, 256>>>(fin, out_tW, out_tb, out);
}

// round 3
// speedup vs baseline: 1.5275x; 1.5275x over previous
#include <cuda_runtime.h>
#include <cuda_bf16.h>
#include <math.h>
#include <stdint.h>

// ---------------------------------------------------------------------------
// Problem constants
// ---------------------------------------------------------------------------
#define TT   256
#define PP   256
#define EE   300
#define HH   256
#define NPOS 65536            // T*P
#define G4   1024             // 4H
#define D2H  512              // 2H
#define NC   4608             // 9 * 512 feature columns
#define MM   50000
#define CC   16384
#define EP   320              // E padded to multiple of 32

// ---------------------------------------------------------------------------
// Device scratch (static allocations only)
// ---------------------------------------------------------------------------
__device__ float    g_GxF[(size_t)NPOS * G4];          // 268 MB
__device__ float    g_GxB[(size_t)NPOS * G4];          // 268 MB
__device__ float    g_flat[(size_t)NPOS * D2H];        // 134 MB [hf | hb]
__device__ float    g_Feat[(size_t)NPOS * NC];         // 1.21 GB
__device__ float    g_cstate[2 * PP * HH];
__device__ unsigned g_pairKeys[(size_t)3 * CC * D2H];  // 100 MB
__device__ unsigned g_triKeys[(size_t)CC * D2H];       // 33 MB
__device__ float    g_pv[(size_t)3 * CC * D2H];        // 100 MB
__device__ float    g_tv[(size_t)CC * D2H];            // 33 MB
__device__ float    g_final[(size_t)CC * D2H];         // 33 MB

// bf16 split operand buffers
__device__ __nv_bfloat16 g_xHi[(size_t)NPOS * EP];     // 42 MB
__device__ __nv_bfloat16 g_xLo[(size_t)NPOS * EP];
__device__ __nv_bfloat16 g_wHiF[(size_t)G4 * EP];
__device__ __nv_bfloat16 g_wLoF[(size_t)G4 * EP];
__device__ __nv_bfloat16 g_wHiB[(size_t)G4 * EP];
__device__ __nv_bfloat16 g_wLoB[(size_t)G4 * EP];
__device__ __nv_bfloat16 g_flatHi[(size_t)NPOS * D2H]; // 67 MB
__device__ __nv_bfloat16 g_flatLo[(size_t)NPOS * D2H];
__device__ __nv_bfloat16 g_BcHi[(size_t)NC * D2H];
__device__ __nv_bfloat16 g_BcLo[(size_t)NC * D2H];
__device__ __nv_bfloat16 g_aWHi[(size_t)D2H * 2048];
__device__ __nv_bfloat16 g_aWLo[(size_t)D2H * 2048];
__device__ __nv_bfloat16 g_ftHi[(size_t)CC * 2048];    // 67 MB
__device__ __nv_bfloat16 g_ftLo[(size_t)CC * 2048];

// ---------------------------------------------------------------------------
// Helpers
// ---------------------------------------------------------------------------
__device__ __forceinline__ uint32_t smem_u32(const void* p) {
    uint32_t a;
    asm("{ .reg .u64 t; cvta.to.shared.u64 t, %1; cvt.u32.u64 %0, t; }"
        : "=r"(a) : "l"(p));
    return a;
}

#define LDSM_X4(r, addr) \
    asm volatile("ldmatrix.sync.aligned.m8n8.x4.shared.b16 {%0,%1,%2,%3}, [%4];" \
        : "=r"((r)[0]), "=r"((r)[1]), "=r"((r)[2]), "=r"((r)[3]) : "r"(addr))

#define MMA_BF16(d, a, b) \
    asm volatile("mma.sync.aligned.m16n8k16.row.col.f32.bf16.bf16.f32 " \
        "{%0,%1,%2,%3}, {%4,%5,%6,%7}, {%8,%9}, {%0,%1,%2,%3};" \
        : "+f"((d)[0]), "+f"((d)[1]), "+f"((d)[2]), "+f"((d)[3]) \
        : "r"((a)[0]), "r"((a)[1]), "r"((a)[2]), "r"((a)[3]), \
          "r"((b)[0]), "r"((b)[1]))

#define CP_ASYNC16(dst, src) \
    asm volatile("cp.async.cg.shared.global [%0], [%1], 16;" \
                 :: "r"(dst), "l"(src))
#define CP_COMMIT() asm volatile("cp.async.commit_group;" ::: "memory")
#define CP_WAIT(n)  asm volatile("cp.async.wait_group %0;" :: "n"(n) : "memory")

__device__ __forceinline__ float sigmoidf_(float x) { return 1.0f / (1.0f + expf(-x)); }

__device__ __forceinline__ unsigned fmap(float f) {
    unsigned b = __float_as_uint(f);
    return (b & 0x80000000u) ? ~b : (b | 0x80000000u);
}
__device__ __forceinline__ float funmap(unsigned u) {
    return (u & 0x80000000u) ? __uint_as_float(u & 0x7FFFFFFFu)
                             : __uint_as_float(~u);
}
__device__ __forceinline__ float warpReduceSum(float v) {
    #pragma unroll
    for (int o = 16; o > 0; o >>= 1) v += __shfl_down_sync(0xffffffffu, v, o);
    return v;
}
__device__ __forceinline__ float blockReduceSum256(float v) {
    __shared__ float sh[8];
    int lane = threadIdx.x & 31, wid = threadIdx.x >> 5;
    v = warpReduceSum(v);
    if (lane == 0) sh[wid] = v;
    __syncthreads();
    v = (threadIdx.x < 8) ? sh[threadIdx.x] : 0.0f;
    if (wid == 0) v = warpReduceSum(v);
    return v;
}
__device__ __forceinline__ void splitbf(float f, __nv_bfloat16& h, __nv_bfloat16& l) {
    h = __float2bfloat16(f);
    l = __float2bfloat16(f - __bfloat162float(h));
}

// ---------------------------------------------------------------------------
// bf16 3-term split GEMM: C[M,N] = A[M,K] @ B[N,K]^T + bias
// grid = (N/128, M/128), 256 threads (8 warps: 2 M x 4 N).
// SMEM: 2 stages x {Ahi, Alo, Bhi, Blo} tiles of 128 rows x 80B stride.
// ---------------------------------------------------------------------------
#define RSZ   80
#define TILEB (128 * RSZ)     // 10240
#define STAGE (4 * TILEB)     // 40960
#define SMEM_GEMM (2 * STAGE) // 81920

__global__ __launch_bounds__(256, 1)
void gemm_bf16x3_kernel(const __nv_bfloat16* __restrict__ Ahi,
                        const __nv_bfloat16* __restrict__ Alo,
                        const __nv_bfloat16* __restrict__ Bhi,
                        const __nv_bfloat16* __restrict__ Blo,
                        const float* __restrict__ bias,
                        float* __restrict__ C, int K) {
    extern __shared__ char smem[];
    const uint32_t sb = smem_u32(smem);
    const int tid = threadIdx.x, lane = tid & 31, wid = tid >> 5;
    const int m0 = blockIdx.y * 128, n0 = blockIdx.x * 128;
    const int ldc = gridDim.x * 128;
    const int wm = wid & 1, wn = wid >> 1;

    float acc[4][4][4];
    #pragma unroll
    for (int i = 0; i < 4; ++i)
        #pragma unroll
        for (int j = 0; j < 4; ++j)
            #pragma unroll
            for (int q = 0; q < 4; ++q) acc[i][j][q] = 0.0f;

    const int nch = K >> 5;

    // per-thread cp.async coords: 2 chunks per array per thread
    const int r0c = (2 * tid) >> 2, ch0 = (2 * tid) & 3;
    const int r1c = (2 * tid + 1) >> 2, ch1 = (2 * tid + 1) & 3;

    // per-thread ldmatrix coords
    const int rA = lane & 15;
    const int cA = lane >> 4;

    // ---- stage load helper (macro-ized to keep pointers restrict) ----
    #define LOAD_STAGE(cc)                                                      \
    do {                                                                        \
        const int kb = (cc) << 5;                                               \
        const uint32_t dst = sb + ((cc) & 1) * STAGE;                           \
        CP_ASYNC16(dst + 0 * TILEB + r0c * RSZ + ch0 * 16,                      \
                   Ahi + (size_t)(m0 + r0c) * K + kb + ch0 * 8);                \
        CP_ASYNC16(dst + 0 * TILEB + r1c * RSZ + ch1 * 16,                      \
                   Ahi + (size_t)(m0 + r1c) * K + kb + ch1 * 8);                \
        CP_ASYNC16(dst + 1 * TILEB + r0c * RSZ + ch0 * 16,                      \
                   Alo + (size_t)(m0 + r0c) * K + kb + ch0 * 8);                \
        CP_ASYNC16(dst + 1 * TILEB + r1c * RSZ + ch1 * 16,                      \
                   Alo + (size_t)(m0 + r1c) * K + kb + ch1 * 8);                \
        CP_ASYNC16(dst + 2 * TILEB + r0c * RSZ + ch0 * 16,                      \
                   Bhi + (size_t)(n0 + r0c) * K + kb + ch0 * 8);                \
        CP_ASYNC16(dst + 2 * TILEB + r1c * RSZ + ch1 * 16,                      \
                   Bhi + (size_t)(n0 + r1c) * K + kb + ch1 * 8);                \
        CP_ASYNC16(dst + 3 * TILEB + r0c * RSZ + ch0 * 16,                      \
                   Blo + (size_t)(n0 + r0c) * K + kb + ch0 * 8);                \
        CP_ASYNC16(dst + 3 * TILEB + r1c * RSZ + ch1 * 16,                      \
                   Blo + (size_t)(n0 + r1c) * K + kb + ch1 * 8);                \
        CP_COMMIT();                                                            \
    } while (0)

    LOAD_STAGE(0);

    for (int c = 0; c < nch; ++c) {
        if (c + 1 < nch) {
            LOAD_STAGE(c + 1);
            CP_WAIT(1);
        } else {
            CP_WAIT(0);
        }
        __syncthreads();

        const uint32_t s = sb + (c & 1) * STAGE;
        const uint32_t aHiB = s, aLoB = s + TILEB;
        const uint32_t bHiB = s + 2 * TILEB, bLoB = s + 3 * TILEB;

        #pragma unroll
        for (int ks = 0; ks < 2; ++ks) {
            uint32_t aHi[4][4], aLo[4][4], bHi[4][2], bLo[4][2];
            #pragma unroll
            for (int mt = 0; mt < 4; ++mt) {
                uint32_t ad = (uint32_t)(wm * 64 + mt * 16 + rA) * RSZ +
                              (uint32_t)(ks * 2 + cA) * 16;
                LDSM_X4(aHi[mt], aHiB + ad);
                LDSM_X4(aLo[mt], aLoB + ad);
            }
            #pragma unroll
            for (int nh = 0; nh < 2; ++nh) {
                uint32_t bd = (uint32_t)(wn * 32 + nh * 16 + rA) * RSZ +
                              (uint32_t)(ks * 2 + cA) * 16;
                uint32_t t[4];
                LDSM_X4(t, bHiB + bd);
                bHi[nh * 2 + 0][0] = t[0]; bHi[nh * 2 + 0][1] = t[2];
                bHi[nh * 2 + 1][0] = t[1]; bHi[nh * 2 + 1][1] = t[3];
                LDSM_X4(t, bLoB + bd);
                bLo[nh * 2 + 0][0] = t[0]; bLo[nh * 2 + 0][1] = t[2];
                bLo[nh * 2 + 1][0] = t[1]; bLo[nh * 2 + 1][1] = t[3];
            }
            #pragma unroll
            for (int mt = 0; mt < 4; ++mt)
                #pragma unroll
                for (int nt = 0; nt < 4; ++nt) {
                    MMA_BF16(acc[mt][nt], aHi[mt], bHi[nt]);
                    MMA_BF16(acc[mt][nt], aLo[mt], bHi[nt]);
                    MMA_BF16(acc[mt][nt], aHi[mt], bLo[nt]);
                }
        }
        __syncthreads();
    }

    // ---- epilogue ----
    const int rr = lane >> 2, cc2 = (lane & 3) * 2;
    #pragma unroll
    for (int mt = 0; mt < 4; ++mt) {
        #pragma unroll
        for (int nt = 0; nt < 4; ++nt) {
            int row = m0 + wm * 64 + mt * 16 + rr;
            int col = n0 + wn * 32 + nt * 8 + cc2;
            float b0 = 0.f, b1 = 0.f;
            if (bias) { b0 = bias[col]; b1 = bias[col + 1]; }
            float2 v0 = make_float2(acc[mt][nt][0] + b0, acc[mt][nt][1] + b1);
            float2 v1 = make_float2(acc[mt][nt][2] + b0, acc[mt][nt][3] + b1);
            *(float2*)&C[(size_t)row * ldc + col] = v0;
            *(float2*)&C[(size_t)(row + 8) * ldc + col] = v1;
        }
    }
    #undef LOAD_STAGE
}

// ---------------------------------------------------------------------------
// Split/pad fp32 -> bf16 hi/lo. dst rows x dk; src rows x sk (zero-pad c>=sk)
// ---------------------------------------------------------------------------
__global__ void split_pad_kernel(const float* __restrict__ src,
                                 __nv_bfloat16* __restrict__ hi,
                                 __nv_bfloat16* __restrict__ lo,
                                 int rows, int sk, int dk) {
    size_t total = (size_t)rows * dk;
    for (size_t idx = blockIdx.x * (size_t)blockDim.x + threadIdx.x; idx < total;
         idx += (size_t)gridDim.x * blockDim.x) {
        int r = (int)(idx / dk), c = (int)(idx % dk);
        float f = (c < sk) ? src[(size_t)r * sk + c] : 0.0f;
        __nv_bfloat16 h, l; splitbf(f, h, l);
        hi[idx] = h; lo[idx] = l;
    }
}

// ---------------------------------------------------------------------------
// Pack transposed concatenated pair/tri weights into bf16 hi/lo [NC,512]
// ---------------------------------------------------------------------------
__global__ void pack_bcatT_kernel(const float* __restrict__ pair_hW,
                                  const float* __restrict__ tri_hW,
                                  __nv_bfloat16* __restrict__ hi,
                                  __nv_bfloat16* __restrict__ lo) {
    const int total = NC * D2H;
    for (int idx = blockIdx.x * blockDim.x + threadIdx.x; idx < total;
         idx += gridDim.x * blockDim.x) {
        int n = idx >> 9, d = idx & 511;
        int q = n >> 9, c = n & 511;
        float v;
        if (q < 6) {
            int k = q >> 1, h = q & 1;
            v = pair_hW[(size_t)k * (G4 * D2H) + (size_t)(h * 512 + d) * D2H + c];
        } else {
            v = tri_hW[(size_t)((q - 6) * 512 + d) * D2H + c];
        }
        __nv_bfloat16 hh, ll; splitbf(v, hh, ll);
        hi[idx] = hh; lo[idx] = ll;
    }
}

// allWT [512,2048] bf16 hi/lo: allWT[n][k] = all_hW[k][n]
__global__ void pack_allWT_kernel(const float* __restrict__ all_hW,
                                  __nv_bfloat16* __restrict__ hi,
                                  __nv_bfloat16* __restrict__ lo) {
    const int total = D2H * 2048;
    for (int idx = blockIdx.x * blockDim.x + threadIdx.x; idx < total;
         idx += gridDim.x * blockDim.x) {
        int n = idx >> 11, k = idx & 2047;
        float v = all_hW[(size_t)k * D2H + n];
        __nv_bfloat16 hh, ll; splitbf(v, hh, ll);
        hi[idx] = hh; lo[idx] = ll;
    }
}

// ---------------------------------------------------------------------------
// Zero the segment-max key arrays
// ---------------------------------------------------------------------------
__global__ void zero_keys_kernel(unsigned* __restrict__ pk, unsigned* __restrict__ tk) {
    const size_t np = (size_t)3 * CC * D2H;
    const size_t nt = (size_t)CC * D2H;
    for (size_t i = blockIdx.x * (size_t)blockDim.x + threadIdx.x; i < np + nt;
         i += (size_t)gridDim.x * blockDim.x) {
        if (i < np) pk[i] = 0u; else tk[i - np] = 0u;
    }
}

// ---------------------------------------------------------------------------
// One recurrent step, both directions (fused GEMM + gates)
// ---------------------------------------------------------------------------
__global__ __launch_bounds__(256)
void lstm_step_kernel(const float* __restrict__ GxF, const float* __restrict__ GxB,
                      const float* __restrict__ whhF, const float* __restrict__ whhB,
                      float* __restrict__ flat, float* __restrict__ cstate, int s) {
    const int dir = blockIdx.z;
    const int tcur = dir ? (TT - 1 - s) : s;
    const int p0 = blockIdx.x * 32;
    const int j0 = blockIdx.y * 32;
    const int tid = threadIdx.x, tx = tid & 31, tyy = tid >> 5;
    const float* Gx = dir ? GxB : GxF;
    const float* whh = dir ? whhB : whhF;
    const int hcol = dir * HH;
    const int nprevT = dir ? (tcur + 1) : (tcur - 1);

    __shared__ float Hs[32][36];
    __shared__ float Ws[4][32][33];

    float acc[4][4];
    #pragma unroll
    for (int i = 0; i < 4; ++i)
        #pragma unroll
        for (int g = 0; g < 4; ++g) acc[i][g] = 0.0f;

    for (int kt = 0; kt < 8; ++kt) {
        const int k0 = kt * 32;
        {
            int r = tid >> 3, c4 = (tid & 7) * 4;
            float4 v = make_float4(0.f, 0.f, 0.f, 0.f);
            if (s > 0)
                v = *(const float4*)&flat[(size_t)(nprevT * PP + p0 + r) * D2H + hcol + k0 + c4];
            *(float4*)&Hs[r][c4] = v;
        }
        #pragma unroll
        for (int i = 0; i < 4; ++i) {
            int lin = tid + i * 256;
            int g = lin >> 8, rest = lin & 255;
            int j = rest >> 3, c4 = (rest & 7) * 4;
            float4 w = *(const float4*)&whh[(size_t)(g * HH + j0 + j) * HH + k0 + c4];
            Ws[g][c4 + 0][j] = w.x;
            Ws[g][c4 + 1][j] = w.y;
            Ws[g][c4 + 2][j] = w.z;
            Ws[g][c4 + 3][j] = w.w;
        }
        __syncthreads();
        #pragma unroll
        for (int kk = 0; kk < 32; ++kk) {
            float b0 = Ws[0][kk][tx], b1 = Ws[1][kk][tx];
            float b2 = Ws[2][kk][tx], b3 = Ws[3][kk][tx];
            #pragma unroll
            for (int i = 0; i < 4; ++i) {
                float a = Hs[tyy + 8 * i][kk];
                acc[i][0] += a * b0;
                acc[i][1] += a * b1;
                acc[i][2] += a * b2;
                acc[i][3] += a * b3;
            }
        }
        __syncthreads();
    }

    const int j = j0 + tx;
    #pragma unroll
    for (int i = 0; i < 4; ++i) {
        const int p = p0 + tyy + 8 * i;
        const size_t n = (size_t)tcur * PP + p;
        float gi = acc[i][0] + Gx[n * G4 + 0 * HH + j];
        float gf = acc[i][1] + Gx[n * G4 + 1 * HH + j];
        float gg = acc[i][2] + Gx[n * G4 + 2 * HH + j];
        float go = acc[i][3] + Gx[n * G4 + 3 * HH + j];
        const size_t ci = (size_t)dir * (PP * HH) + (size_t)p * HH + j;
        float c = (s == 0) ? 0.0f : cstate[ci];
        float cn = sigmoidf_(gf) * c + sigmoidf_(gi) * tanhf(gg);
        float h = sigmoidf_(go) * tanhf(cn);
        cstate[ci] = cn;
        flat[n * D2H + hcol + j] = h;
    }
}

// ---------------------------------------------------------------------------
// Scatter-max kernels
// ---------------------------------------------------------------------------
__global__ void pair_scatter_kernel(const float* __restrict__ Feat,
                                    const int* __restrict__ occ1,
                                    const int* __restrict__ occ2,
                                    const int* __restrict__ seg,
                                    unsigned* __restrict__ keys) {
    const int b = blockIdx.x;
    const int k = b / MM, m = b % MM;
    const int o1 = occ1[k * MM + m];
    const int o2 = occ2[k * MM + m];
    const int sg = seg[k * MM + m];
    const float* f1 = Feat + (size_t)o1 * NC + (size_t)(2 * k) * 512;
    const float* f2 = Feat + (size_t)o2 * NC + (size_t)(2 * k + 1) * 512;
    unsigned* dst = keys + ((size_t)k * CC + sg) * D2H;
    const int c = threadIdx.x;
    float r = f1[c] + f2[c];
    atomicMax(&dst[c], fmap(r));
}

__global__ void tri_scatter_kernel(const float* __restrict__ Feat,
                                   const int* __restrict__ o1,
                                   const int* __restrict__ o2,
                                   const int* __restrict__ o3,
                                   const int* __restrict__ tseg,
                                   unsigned* __restrict__ keys) {
    const int m = blockIdx.x;
    const int a = o1[m], bb = o2[m], d = o3[m];
    const int sg = tseg[m];
    const float* f1 = Feat + (size_t)a * NC + 6 * 512;
    const float* f2 = Feat + (size_t)bb * NC + 7 * 512;
    const float* f3 = Feat + (size_t)d * NC + 8 * 512;
    unsigned* dst = keys + (size_t)sg * D2H;
    const int c = threadIdx.x;
    float r = f1[c] + f2[c] + f3[c];
    atomicMax(&dst[c], fmap(r));
}

// ---------------------------------------------------------------------------
// Finalize kernels
// ---------------------------------------------------------------------------
__global__ __launch_bounds__(256)
void pair_final_kernel(const unsigned* __restrict__ keys,
                       const float* __restrict__ hb,
                       const float* __restrict__ backoff,
                       const float* __restrict__ oW,
                       const float* __restrict__ ob,
                       float* __restrict__ pv, float* __restrict__ out) {
    const int b = blockIdx.x;
    const int k = b >> 14;
    const unsigned* src = keys + (size_t)b * D2H;
    float partial = 0.0f;
    #pragma unroll
    for (int it = 0; it < 2; ++it) {
        int c = threadIdx.x + it * 256;
        unsigned u = src[c];
        float val = u ? (funmap(u) + hb[k * D2H + c]) : backoff[k * D2H + c];
        float t = tanhf(val);
        pv[(size_t)b * D2H + c] = t;
        partial += t * oW[k * D2H + c];
    }
    float tot = blockReduceSum256(partial);
    if (threadIdx.x == 0) out[CC + b] = tot + ob[k];
}

__global__ __launch_bounds__(256)
void tri_final_kernel(const unsigned* __restrict__ keys,
                      const float* __restrict__ hb,
                      const float* __restrict__ backoff,
                      float* __restrict__ tv) {
    const int s = blockIdx.x;
    const unsigned* src = keys + (size_t)s * D2H;
    #pragma unroll
    for (int it = 0; it < 2; ++it) {
        int c = threadIdx.x + it * 256;
        unsigned u = src[c];
        float val = u ? (funmap(u) + hb[c]) : backoff[c];
        tv[(size_t)s * D2H + c] = tanhf(val);
    }
}

// gather 8H features and split to bf16 hi/lo
__global__ void gather_feats_kernel(const float* __restrict__ pv,
                                    const float* __restrict__ tv,
                                    const int* __restrict__ tpi,
                                    __nv_bfloat16* __restrict__ fhi,
                                    __nv_bfloat16* __restrict__ flo) {
    const int s = blockIdx.x;
    const int i0 = tpi[s * 3 + 0];
    const int i1 = tpi[s * 3 + 1];
    const int i2 = tpi[s * 3 + 2];
    for (int j = threadIdx.x; j < 2048; j += blockDim.x) {
        int q = j >> 9, c = j & 511;
        float v;
        if (q == 0)      v = pv[((size_t)2 * CC + i0) * D2H + c];
        else if (q == 1) v = pv[((size_t)1 * CC + i1) * D2H + c];
        else if (q == 2) v = pv[(size_t)i2 * D2H + c];
        else             v = tv[(size_t)s * D2H + c];
        __nv_bfloat16 h, l; splitbf(v, h, l);
        fhi[(size_t)s * 2048 + j] = h;
        flo[(size_t)s * 2048 + j] = l;
    }
}

__global__ __launch_bounds__(256)
void triple_logit_kernel(const float* __restrict__ fin,
                         const float* __restrict__ tW,
                         const float* __restrict__ tb,
                         float* __restrict__ out) {
    const int s = blockIdx.x;
    float partial = 0.0f;
    #pragma unroll
    for (int it = 0; it < 2; ++it) {
        int c = threadIdx.x + it * 256;
        float v = fin[(size_t)s * D2H + c];
        v = v > 0.0f ? v : 0.0f;
        partial += v * tW[c];
    }
    float tot = blockReduceSum256(partial);
    if (threadIdx.x == 0) out[s] = tot + tb[0];
}

// ---------------------------------------------------------------------------
// Launcher
// ---------------------------------------------------------------------------
extern "C" void kernel_launch(void* const* d_in, const int* in_sizes, int n_in,
                              void* d_out, int out_size) {
    const float* x        = (const float*)d_in[0];
    const float* wih_f    = (const float*)d_in[1];
    const float* whh_f    = (const float*)d_in[2];
    const float* b_f      = (const float*)d_in[3];
    const float* wih_b    = (const float*)d_in[4];
    const float* whh_b    = (const float*)d_in[5];
    const float* b_b      = (const float*)d_in[6];
    const float* pair_hW  = (const float*)d_in[7];
    const float* pair_hb  = (const float*)d_in[8];
    const float* pair_oW  = (const float*)d_in[9];
    const float* pair_ob  = (const float*)d_in[10];
    const float* pair_bo  = (const float*)d_in[11];
    const float* tri_hW   = (const float*)d_in[12];
    const float* tri_hb   = (const float*)d_in[13];
    const float* tri_bo   = (const float*)d_in[14];
    const float* all_hW   = (const float*)d_in[15];
    const float* all_hb   = (const float*)d_in[16];
    const float* out_tW   = (const float*)d_in[17];
    const float* out_tb   = (const float*)d_in[18];
    const int*   occ1     = (const int*)d_in[19];
    const int*   occ2     = (const int*)d_in[20];
    const int*   seg      = (const int*)d_in[21];
    const int*   tri_o1   = (const int*)d_in[22];
    const int*   tri_o2   = (const int*)d_in[23];
    const int*   tri_o3   = (const int*)d_in[24];
    const int*   tri_seg  = (const int*)d_in[25];
    const int*   tri_pi   = (const int*)d_in[26];
    float* out = (float*)d_out;

    float *GxF, *GxB, *flat, *Feat, *cst, *pv, *tv, *fin;
    unsigned *pk, *tk;
    __nv_bfloat16 *xHi, *xLo, *wHiF, *wLoF, *wHiB, *wLoB, *flHi, *flLo;
    __nv_bfloat16 *bcHi, *bcLo, *awHi, *awLo, *ftHi, *ftLo;
    cudaGetSymbolAddress((void**)&GxF,  g_GxF);
    cudaGetSymbolAddress((void**)&GxB,  g_GxB);
    cudaGetSymbolAddress((void**)&flat, g_flat);
    cudaGetSymbolAddress((void**)&Feat, g_Feat);
    cudaGetSymbolAddress((void**)&cst,  g_cstate);
    cudaGetSymbolAddress((void**)&pk,   g_pairKeys);
    cudaGetSymbolAddress((void**)&tk,   g_triKeys);
    cudaGetSymbolAddress((void**)&pv,   g_pv);
    cudaGetSymbolAddress((void**)&tv,   g_tv);
    cudaGetSymbolAddress((void**)&fin,  g_final);
    cudaGetSymbolAddress((void**)&xHi,  g_xHi);
    cudaGetSymbolAddress((void**)&xLo,  g_xLo);
    cudaGetSymbolAddress((void**)&wHiF, g_wHiF);
    cudaGetSymbolAddress((void**)&wLoF, g_wLoF);
    cudaGetSymbolAddress((void**)&wHiB, g_wHiB);
    cudaGetSymbolAddress((void**)&wLoB, g_wLoB);
    cudaGetSymbolAddress((void**)&flHi, g_flatHi);
    cudaGetSymbolAddress((void**)&flLo, g_flatLo);
    cudaGetSymbolAddress((void**)&bcHi, g_BcHi);
    cudaGetSymbolAddress((void**)&bcLo, g_BcLo);
    cudaGetSymbolAddress((void**)&awHi, g_aWHi);
    cudaGetSymbolAddress((void**)&awLo, g_aWLo);
    cudaGetSymbolAddress((void**)&ftHi, g_ftHi);
    cudaGetSymbolAddress((void**)&ftLo, g_ftLo);

    cudaFuncSetAttribute(gemm_bf16x3_kernel,
                         cudaFuncAttributeMaxDynamicSharedMemorySize, SMEM_GEMM);

    // 1) split/pack operands to bf16 hi/lo
    split_pad_kernel<<<4096, 256>>>(x, xHi, xLo, NPOS, EE, EP);
    split_pad_kernel<<<512, 256>>>(wih_f, wHiF, wLoF, G4, EE, EP);
    split_pad_kernel<<<512, 256>>>(wih_b, wHiB, wLoB, G4, EE, EP);
    pack_bcatT_kernel<<<2304, 256>>>(pair_hW, tri_hW, bcHi, bcLo);
    pack_allWT_kernel<<<1024, 256>>>(all_hW, awHi, awLo);

    // 2) input projections: Gx = x @ wih^T + b
    gemm_bf16x3_kernel<<<dim3(8, 512), 256, SMEM_GEMM>>>(xHi, xLo, wHiF, wLoF, b_f, GxF, EP);
    gemm_bf16x3_kernel<<<dim3(8, 512), 256, SMEM_GEMM>>>(xHi, xLo, wHiB, wLoB, b_b, GxB, EP);

    // 3) zero segment-max keys
    zero_keys_kernel<<<32768, 256>>>(pk, tk);

    // 4) BiLSTM recurrence (256 fused steps)
    for (int s = 0; s < TT; ++s)
        lstm_step_kernel<<<dim3(PP / 32, HH / 32, 2), 256>>>(GxF, GxB, whh_f, whh_b, flat, cst, s);

    // 5) split flat, then dense feature transform: Feat = flat @ BcatT^T
    split_pad_kernel<<<8192, 256>>>(flat, flHi, flLo, NPOS, D2H, D2H);
    gemm_bf16x3_kernel<<<dim3(NC / 128, NPOS / 128), 256, SMEM_GEMM>>>(
        flHi, flLo, bcHi, bcLo, nullptr, Feat, D2H);

    // 6) segment max pooling
    pair_scatter_kernel<<<3 * MM, 512>>>(Feat, occ1, occ2, seg, pk);
    tri_scatter_kernel<<<MM, 512>>>(Feat, tri_o1, tri_o2, tri_o3, tri_seg, tk);

    // 7) finalize pooled vectors (+ pair logits)
    pair_final_kernel<<<3 * CC, 256>>>(pk, pair_hb, pair_bo, pair_oW, pair_ob, pv, out);
    tri_final_kernel<<<CC, 256>>>(tk, tri_hb, tri_bo, tv);

    // 8) final MLP + triple logits
    gather_feats_kernel<<<CC, 256>>>(pv, tv, tri_pi, ftHi, ftLo);
    gemm_bf16x3_kernel<<<dim3(D2H / 128, CC / 128), 256, SMEM_GEMM>>>(
        ftHi, ftLo, awHi, awLo, all_hb, fin, 2048);
    triple_logit_kernel<<<CC, 256>>>(fin, out_tW, out_tb, out);
}

// round 4
// speedup vs baseline: 1.5955x; 1.0445x over previous
#include <cuda_runtime.h>
#include <cuda_bf16.h>
#include <math.h>
#include <stdint.h>

// ---------------------------------------------------------------------------
// Problem constants
// ---------------------------------------------------------------------------
#define TT   256
#define PP   256
#define EE   300
#define HH   256
#define NPOS 65536            // T*P
#define G4   1024             // 4H
#define D2H  512              // 2H
#define NC   4608             // 9 * 512 feature columns
#define MM   50000
#define CC   16384
#define EP   320              // E padded to multiple of 32

// ---------------------------------------------------------------------------
// Device scratch (static allocations only)
// ---------------------------------------------------------------------------
__device__ float    g_GxF[(size_t)NPOS * G4];          // 268 MB
__device__ float    g_GxB[(size_t)NPOS * G4];          // 268 MB
__device__ float    g_flat[(size_t)NPOS * D2H];        // 134 MB [hf | hb]
__device__ float    g_Feat[(size_t)NPOS * NC];         // 1.21 GB
__device__ float    g_cstate[2 * PP * HH];
__device__ unsigned g_pairKeys[(size_t)3 * CC * D2H];  // 100 MB
__device__ unsigned g_triKeys[(size_t)CC * D2H];       // 33 MB
__device__ float    g_pv[(size_t)3 * CC * D2H];        // 100 MB
__device__ float    g_tv[(size_t)CC * D2H];            // 33 MB
__device__ float    g_final[(size_t)CC * D2H];         // 33 MB

// bf16 split operand buffers
__device__ __nv_bfloat16 g_xHi[(size_t)NPOS * EP];     // 42 MB
__device__ __nv_bfloat16 g_xLo[(size_t)NPOS * EP];
__device__ __nv_bfloat16 g_wHiF[(size_t)G4 * EP];
__device__ __nv_bfloat16 g_wLoF[(size_t)G4 * EP];
__device__ __nv_bfloat16 g_wHiB[(size_t)G4 * EP];
__device__ __nv_bfloat16 g_wLoB[(size_t)G4 * EP];
__device__ __nv_bfloat16 g_flatHi[(size_t)NPOS * D2H]; // 67 MB
__device__ __nv_bfloat16 g_flatLo[(size_t)NPOS * D2H];
__device__ __nv_bfloat16 g_BcHi[(size_t)NC * D2H];
__device__ __nv_bfloat16 g_BcLo[(size_t)NC * D2H];
__device__ __nv_bfloat16 g_aWHi[(size_t)D2H * 2048];
__device__ __nv_bfloat16 g_aWLo[(size_t)D2H * 2048];
__device__ __nv_bfloat16 g_ftHi[(size_t)CC * 2048];    // 67 MB
__device__ __nv_bfloat16 g_ftLo[(size_t)CC * 2048];

// ---------------------------------------------------------------------------
// Helpers
// ---------------------------------------------------------------------------
__device__ __forceinline__ uint32_t smem_u32(const void* p) {
    uint32_t a;
    asm("{ .reg .u64 t; cvta.to.shared.u64 t, %1; cvt.u32.u64 %0, t; }"
        : "=r"(a) : "l"(p));
    return a;
}

#define LDSM_X4(r, addr) \
    asm volatile("ldmatrix.sync.aligned.m8n8.x4.shared.b16 {%0,%1,%2,%3}, [%4];" \
        : "=r"((r)[0]), "=r"((r)[1]), "=r"((r)[2]), "=r"((r)[3]) : "r"(addr))

#define MMA_BF16(d, a, b) \
    asm volatile("mma.sync.aligned.m16n8k16.row.col.f32.bf16.bf16.f32 " \
        "{%0,%1,%2,%3}, {%4,%5,%6,%7}, {%8,%9}, {%0,%1,%2,%3};" \
        : "+f"((d)[0]), "+f"((d)[1]), "+f"((d)[2]), "+f"((d)[3]) \
        : "r"((a)[0]), "r"((a)[1]), "r"((a)[2]), "r"((a)[3]), \
          "r"((b)[0]), "r"((b)[1]))

#define CP_ASYNC16(dst, src) \
    asm volatile("cp.async.cg.shared.global [%0], [%1], 16;" \
                 :: "r"(dst), "l"(src))
#define CP_COMMIT() asm volatile("cp.async.commit_group;" ::: "memory")
#define CP_WAIT(n)  asm volatile("cp.async.wait_group %0;" :: "n"(n) : "memory")

__device__ __forceinline__ float sigmoidf_(float x) { return 1.0f / (1.0f + expf(-x)); }

__device__ __forceinline__ unsigned fmap(float f) {
    unsigned b = __float_as_uint(f);
    return (b & 0x80000000u) ? ~b : (b | 0x80000000u);
}
__device__ __forceinline__ float funmap(unsigned u) {
    return (u & 0x80000000u) ? __uint_as_float(u & 0x7FFFFFFFu)
                             : __uint_as_float(~u);
}
__device__ __forceinline__ float warpReduceSum(float v) {
    #pragma unroll
    for (int o = 16; o > 0; o >>= 1) v += __shfl_down_sync(0xffffffffu, v, o);
    return v;
}
__device__ __forceinline__ float blockReduceSum256(float v) {
    __shared__ float sh[8];
    int lane = threadIdx.x & 31, wid = threadIdx.x >> 5;
    v = warpReduceSum(v);
    if (lane == 0) sh[wid] = v;
    __syncthreads();
    v = (threadIdx.x < 8) ? sh[threadIdx.x] : 0.0f;
    if (wid == 0) v = warpReduceSum(v);
    return v;
}
__device__ __forceinline__ void splitbf(float f, __nv_bfloat16& h, __nv_bfloat16& l) {
    h = __float2bfloat16(f);
    l = __float2bfloat16(f - __bfloat162float(h));
}

// ---------------------------------------------------------------------------
// bf16 3-term split GEMM v2: C[M,N] = A[M,K] @ B[N,K]^T + bias
// CTA tile 128x256, 512 threads (16 warps as 2m x 8n; warp tile 64x32).
// 3-stage cp.async pipeline, K-chunk = 32. RSZ=80 (conflict-free ldmatrix).
// ---------------------------------------------------------------------------
#define RSZ     80
#define ST_AHI  0
#define ST_ALO  10240               // 128*80
#define ST_BHI  20480
#define ST_BLO  40960               // 20480 + 256*80
#define STAGE_B 61440               // (128+128+256+256)*80
#define SMEM_GEMM (3 * STAGE_B)     // 184320

__global__ __launch_bounds__(512, 1)
void gemm_bf16x3_kernel(const __nv_bfloat16* __restrict__ Ahi,
                        const __nv_bfloat16* __restrict__ Alo,
                        const __nv_bfloat16* __restrict__ Bhi,
                        const __nv_bfloat16* __restrict__ Blo,
                        const float* __restrict__ bias,
                        float* __restrict__ C, int K) {
    extern __shared__ char smem[];
    const uint32_t sb = smem_u32(smem);
    const int tid = threadIdx.x, lane = tid & 31, wid = tid >> 5;
    const int m0 = blockIdx.y * 128, n0 = blockIdx.x * 256;
    const int ldc = gridDim.x * 256;
    const int wm = wid & 1, wn = wid >> 1;   // wm 0..1, wn 0..7

    float acc[4][4][4];
    #pragma unroll
    for (int i = 0; i < 4; ++i)
        #pragma unroll
        for (int j = 0; j < 4; ++j)
            #pragma unroll
            for (int q = 0; q < 4; ++q) acc[i][j][q] = 0.0f;

    const int nch = K >> 5;

    // cp.async coords
    const int rA = tid >> 2, chA = tid & 3;                 // A: 512 chunks
    const int rB0 = tid >> 2, cB0 = tid & 3;                // B: first 512
    const int rB1 = (tid + 512) >> 2, cB1 = tid & 3;        // B: second 512

    #define LOAD_STAGE(cc, st)                                                  \
    do {                                                                        \
        const int kb = (cc) << 5;                                               \
        const uint32_t dst = sb + (uint32_t)(st) * STAGE_B;                     \
        CP_ASYNC16(dst + ST_AHI + rA * RSZ + chA * 16,                          \
                   Ahi + (size_t)(m0 + rA) * K + kb + chA * 8);                 \
        CP_ASYNC16(dst + ST_ALO + rA * RSZ + chA * 16,                          \
                   Alo + (size_t)(m0 + rA) * K + kb + chA * 8);                 \
        CP_ASYNC16(dst + ST_BHI + rB0 * RSZ + cB0 * 16,                         \
                   Bhi + (size_t)(n0 + rB0) * K + kb + cB0 * 8);                \
        CP_ASYNC16(dst + ST_BHI + rB1 * RSZ + cB1 * 16,                         \
                   Bhi + (size_t)(n0 + rB1) * K + kb + cB1 * 8);                \
        CP_ASYNC16(dst + ST_BLO + rB0 * RSZ + cB0 * 16,                         \
                   Blo + (size_t)(n0 + rB0) * K + kb + cB0 * 8);                \
        CP_ASYNC16(dst + ST_BLO + rB1 * RSZ + cB1 * 16,                         \
                   Blo + (size_t)(n0 + rB1) * K + kb + cB1 * 8);                \
        CP_COMMIT();                                                            \
    } while (0)

    LOAD_STAGE(0, 0);
    if (nch > 1) LOAD_STAGE(1, 1);

    int st = 0;
    for (int c = 0; c < nch; ++c) {
        if (c + 2 < nch) {
            int st2 = st + 2; if (st2 >= 3) st2 -= 3;
            LOAD_STAGE(c + 2, st2);
            CP_WAIT(2);
        } else if (c + 1 < nch) {
            CP_WAIT(1);
        } else {
            CP_WAIT(0);
        }
        __syncthreads();

        const uint32_t s = sb + (uint32_t)st * STAGE_B;

        #pragma unroll
        for (int ks = 0; ks < 2; ++ks) {
            const uint32_t colOff = (uint32_t)(ks * 2 + (lane >> 4)) * 16;
            uint32_t aHi[4][4], bHi[4][2];
            // --- term 1: aHi x bHi ---
            #pragma unroll
            for (int mt = 0; mt < 4; ++mt) {
                uint32_t ad = (uint32_t)(wm * 64 + mt * 16 + (lane & 15)) * RSZ + colOff;
                LDSM_X4(aHi[mt], s + ST_AHI + ad);
            }
            #pragma unroll
            for (int nh = 0; nh < 2; ++nh) {
                uint32_t bd = (uint32_t)(wn * 32 + nh * 16 + (lane & 15)) * RSZ + colOff;
                uint32_t t[4];
                LDSM_X4(t, s + ST_BHI + bd);
                bHi[nh * 2 + 0][0] = t[0]; bHi[nh * 2 + 0][1] = t[2];
                bHi[nh * 2 + 1][0] = t[1]; bHi[nh * 2 + 1][1] = t[3];
            }
            #pragma unroll
            for (int mt = 0; mt < 4; ++mt)
                #pragma unroll
                for (int nt = 0; nt < 4; ++nt)
                    MMA_BF16(acc[mt][nt], aHi[mt], bHi[nt]);
            // --- term 2: aLo x bHi (aLo transient) ---
            {
                uint32_t aLo[4][4];
                #pragma unroll
                for (int mt = 0; mt < 4; ++mt) {
                    uint32_t ad = (uint32_t)(wm * 64 + mt * 16 + (lane & 15)) * RSZ + colOff;
                    LDSM_X4(aLo[mt], s + ST_ALO + ad);
                }
                #pragma unroll
                for (int mt = 0; mt < 4; ++mt)
                    #pragma unroll
                    for (int nt = 0; nt < 4; ++nt)
                        MMA_BF16(acc[mt][nt], aLo[mt], bHi[nt]);
            }
            // --- term 3: aHi x bLo (bLo transient) ---
            {
                uint32_t bLo[4][2];
                #pragma unroll
                for (int nh = 0; nh < 2; ++nh) {
                    uint32_t bd = (uint32_t)(wn * 32 + nh * 16 + (lane & 15)) * RSZ + colOff;
                    uint32_t t[4];
                    LDSM_X4(t, s + ST_BLO + bd);
                    bLo[nh * 2 + 0][0] = t[0]; bLo[nh * 2 + 0][1] = t[2];
                    bLo[nh * 2 + 1][0] = t[1]; bLo[nh * 2 + 1][1] = t[3];
                }
                #pragma unroll
                for (int mt = 0; mt < 4; ++mt)
                    #pragma unroll
                    for (int nt = 0; nt < 4; ++nt)
                        MMA_BF16(acc[mt][nt], aHi[mt], bLo[nt]);
            }
        }
        __syncthreads();
        if (++st >= 3) st -= 3;
    }

    // ---- epilogue ----
    const int rr = lane >> 2, cc2 = (lane & 3) * 2;
    #pragma unroll
    for (int mt = 0; mt < 4; ++mt) {
        #pragma unroll
        for (int nt = 0; nt < 4; ++nt) {
            int row = m0 + wm * 64 + mt * 16 + rr;
            int col = n0 + wn * 32 + nt * 8 + cc2;
            float b0 = 0.f, b1 = 0.f;
            if (bias) { b0 = bias[col]; b1 = bias[col + 1]; }
            float2 v0 = make_float2(acc[mt][nt][0] + b0, acc[mt][nt][1] + b1);
            float2 v1 = make_float2(acc[mt][nt][2] + b0, acc[mt][nt][3] + b1);
            *(float2*)&C[(size_t)row * ldc + col] = v0;
            *(float2*)&C[(size_t)(row + 8) * ldc + col] = v1;
        }
    }
    #undef LOAD_STAGE
}

// ---------------------------------------------------------------------------
// Split/pad fp32 -> bf16 hi/lo. dst rows x dk; src rows x sk (zero-pad c>=sk)
// ---------------------------------------------------------------------------
__global__ void split_pad_kernel(const float* __restrict__ src,
                                 __nv_bfloat16* __restrict__ hi,
                                 __nv_bfloat16* __restrict__ lo,
                                 int rows, int sk, int dk) {
    size_t total = (size_t)rows * dk;
    for (size_t idx = blockIdx.x * (size_t)blockDim.x + threadIdx.x; idx < total;
         idx += (size_t)gridDim.x * blockDim.x) {
        int r = (int)(idx / dk), c = (int)(idx % dk);
        float f = (c < sk) ? src[(size_t)r * sk + c] : 0.0f;
        __nv_bfloat16 h, l; splitbf(f, h, l);
        hi[idx] = h; lo[idx] = l;
    }
}

// ---------------------------------------------------------------------------
// Pack transposed concatenated pair/tri weights into bf16 hi/lo [NC,512]
// ---------------------------------------------------------------------------
__global__ void pack_bcatT_kernel(const float* __restrict__ pair_hW,
                                  const float* __restrict__ tri_hW,
                                  __nv_bfloat16* __restrict__ hi,
                                  __nv_bfloat16* __restrict__ lo) {
    const int total = NC * D2H;
    for (int idx = blockIdx.x * blockDim.x + threadIdx.x; idx < total;
         idx += gridDim.x * blockDim.x) {
        int n = idx >> 9, d = idx & 511;
        int q = n >> 9, c = n & 511;
        float v;
        if (q < 6) {
            int k = q >> 1, h = q & 1;
            v = pair_hW[(size_t)k * (G4 * D2H) + (size_t)(h * 512 + d) * D2H + c];
        } else {
            v = tri_hW[(size_t)((q - 6) * 512 + d) * D2H + c];
        }
        __nv_bfloat16 hh, ll; splitbf(v, hh, ll);
        hi[idx] = hh; lo[idx] = ll;
    }
}

// allWT [512,2048] bf16 hi/lo: allWT[n][k] = all_hW[k][n]
__global__ void pack_allWT_kernel(const float* __restrict__ all_hW,
                                  __nv_bfloat16* __restrict__ hi,
                                  __nv_bfloat16* __restrict__ lo) {
    const int total = D2H * 2048;
    for (int idx = blockIdx.x * blockDim.x + threadIdx.x; idx < total;
         idx += gridDim.x * blockDim.x) {
        int n = idx >> 11, k = idx & 2047;
        float v = all_hW[(size_t)k * D2H + n];
        __nv_bfloat16 hh, ll; splitbf(v, hh, ll);
        hi[idx] = hh; lo[idx] = ll;
    }
}

// ---------------------------------------------------------------------------
// Zero the segment-max key arrays
// ---------------------------------------------------------------------------
__global__ void zero_keys_kernel(unsigned* __restrict__ pk, unsigned* __restrict__ tk) {
    const size_t np = (size_t)3 * CC * D2H;
    const size_t nt = (size_t)CC * D2H;
    for (size_t i = blockIdx.x * (size_t)blockDim.x + threadIdx.x; i < np + nt;
         i += (size_t)gridDim.x * blockDim.x) {
        if (i < np) pk[i] = 0u; else tk[i - np] = 0u;
    }
}

// ---------------------------------------------------------------------------
// One recurrent step, both directions (fused GEMM + gates + bf16 split)
// ---------------------------------------------------------------------------
__global__ __launch_bounds__(256)
void lstm_step_kernel(const float* __restrict__ GxF, const float* __restrict__ GxB,
                      const float* __restrict__ whhF, const float* __restrict__ whhB,
                      float* __restrict__ flat,
                      __nv_bfloat16* __restrict__ flatHi,
                      __nv_bfloat16* __restrict__ flatLo,
                      float* __restrict__ cstate, int s) {
    const int dir = blockIdx.z;
    const int tcur = dir ? (TT - 1 - s) : s;
    const int p0 = blockIdx.x * 32;
    const int j0 = blockIdx.y * 32;
    const int tid = threadIdx.x, tx = tid & 31, tyy = tid >> 5;
    const float* Gx = dir ? GxB : GxF;
    const float* whh = dir ? whhB : whhF;
    const int hcol = dir * HH;
    const int nprevT = dir ? (tcur + 1) : (tcur - 1);

    __shared__ float Hs[32][36];
    __shared__ float Ws[4][32][33];

    float acc[4][4];
    #pragma unroll
    for (int i = 0; i < 4; ++i)
        #pragma unroll
        for (int g = 0; g < 4; ++g) acc[i][g] = 0.0f;

    for (int kt = 0; kt < 8; ++kt) {
        const int k0 = kt * 32;
        {
            int r = tid >> 3, c4 = (tid & 7) * 4;
            float4 v = make_float4(0.f, 0.f, 0.f, 0.f);
            if (s > 0)
                v = *(const float4*)&flat[(size_t)(nprevT * PP + p0 + r) * D2H + hcol + k0 + c4];
            *(float4*)&Hs[r][c4] = v;
        }
        #pragma unroll
        for (int i = 0; i < 4; ++i) {
            int lin = tid + i * 256;
            int g = lin >> 8, rest = lin & 255;
            int j = rest >> 3, c4 = (rest & 7) * 4;
            float4 w = *(const float4*)&whh[(size_t)(g * HH + j0 + j) * HH + k0 + c4];
            Ws[g][c4 + 0][j] = w.x;
            Ws[g][c4 + 1][j] = w.y;
            Ws[g][c4 + 2][j] = w.z;
            Ws[g][c4 + 3][j] = w.w;
        }
        __syncthreads();
        #pragma unroll
        for (int kk = 0; kk < 32; ++kk) {
            float b0 = Ws[0][kk][tx], b1 = Ws[1][kk][tx];
            float b2 = Ws[2][kk][tx], b3 = Ws[3][kk][tx];
            #pragma unroll
            for (int i = 0; i < 4; ++i) {
                float a = Hs[tyy + 8 * i][kk];
                acc[i][0] += a * b0;
                acc[i][1] += a * b1;
                acc[i][2] += a * b2;
                acc[i][3] += a * b3;
            }
        }
        __syncthreads();
    }

    const int j = j0 + tx;
    #pragma unroll
    for (int i = 0; i < 4; ++i) {
        const int p = p0 + tyy + 8 * i;
        const size_t n = (size_t)tcur * PP + p;
        float gi = acc[i][0] + Gx[n * G4 + 0 * HH + j];
        float gf = acc[i][1] + Gx[n * G4 + 1 * HH + j];
        float gg = acc[i][2] + Gx[n * G4 + 2 * HH + j];
        float go = acc[i][3] + Gx[n * G4 + 3 * HH + j];
        const size_t ci = (size_t)dir * (PP * HH) + (size_t)p * HH + j;
        float c = (s == 0) ? 0.0f : cstate[ci];
        float cn = sigmoidf_(gf) * c + sigmoidf_(gi) * tanhf(gg);
        float h = sigmoidf_(go) * tanhf(cn);
        cstate[ci] = cn;
        flat[n * D2H + hcol + j] = h;
        __nv_bfloat16 hh, hl; splitbf(h, hh, hl);
        flatHi[n * D2H + hcol + j] = hh;
        flatLo[n * D2H + hcol + j] = hl;
    }
}

// ---------------------------------------------------------------------------
// Scatter-max kernels
// ---------------------------------------------------------------------------
__global__ void pair_scatter_kernel(const float* __restrict__ Feat,
                                    const int* __restrict__ occ1,
                                    const int* __restrict__ occ2,
                                    const int* __restrict__ seg,
                                    unsigned* __restrict__ keys) {
    const int b = blockIdx.x;
    const int k = b / MM, m = b % MM;
    const int o1 = occ1[k * MM + m];
    const int o2 = occ2[k * MM + m];
    const int sg = seg[k * MM + m];
    const float* f1 = Feat + (size_t)o1 * NC + (size_t)(2 * k) * 512;
    const float* f2 = Feat + (size_t)o2 * NC + (size_t)(2 * k + 1) * 512;
    unsigned* dst = keys + ((size_t)k * CC + sg) * D2H;
    const int c = threadIdx.x;
    float r = f1[c] + f2[c];
    atomicMax(&dst[c], fmap(r));
}

__global__ void tri_scatter_kernel(const float* __restrict__ Feat,
                                   const int* __restrict__ o1,
                                   const int* __restrict__ o2,
                                   const int* __restrict__ o3,
                                   const int* __restrict__ tseg,
                                   unsigned* __restrict__ keys) {
    const int m = blockIdx.x;
    const int a = o1[m], bb = o2[m], d = o3[m];
    const int sg = tseg[m];
    const float* f1 = Feat + (size_t)a * NC + 6 * 512;
    const float* f2 = Feat + (size_t)bb * NC + 7 * 512;
    const float* f3 = Feat + (size_t)d * NC + 8 * 512;
    unsigned* dst = keys + (size_t)sg * D2H;
    const int c = threadIdx.x;
    float r = f1[c] + f2[c] + f3[c];
    atomicMax(&dst[c], fmap(r));
}

// ---------------------------------------------------------------------------
// Finalize kernels
// ---------------------------------------------------------------------------
__global__ __launch_bounds__(256)
void pair_final_kernel(const unsigned* __restrict__ keys,
                       const float* __restrict__ hb,
                       const float* __restrict__ backoff,
                       const float* __restrict__ oW,
                       const float* __restrict__ ob,
                       float* __restrict__ pv, float* __restrict__ out) {
    const int b = blockIdx.x;
    const int k = b >> 14;
    const unsigned* src = keys + (size_t)b * D2H;
    float partial = 0.0f;
    #pragma unroll
    for (int it = 0; it < 2; ++it) {
        int c = threadIdx.x + it * 256;
        unsigned u = src[c];
        float val = u ? (funmap(u) + hb[k * D2H + c]) : backoff[k * D2H + c];
        float t = tanhf(val);
        pv[(size_t)b * D2H + c] = t;
        partial += t * oW[k * D2H + c];
    }
    float tot = blockReduceSum256(partial);
    if (threadIdx.x == 0) out[CC + b] = tot + ob[k];
}

__global__ __launch_bounds__(256)
void tri_final_kernel(const unsigned* __restrict__ keys,
                      const float* __restrict__ hb,
                      const float* __restrict__ backoff,
                      float* __restrict__ tv) {
    const int s = blockIdx.x;
    const unsigned* src = keys + (size_t)s * D2H;
    #pragma unroll
    for (int it = 0; it < 2; ++it) {
        int c = threadIdx.x + it * 256;
        unsigned u = src[c];
        float val = u ? (funmap(u) + hb[c]) : backoff[c];
        tv[(size_t)s * D2H + c] = tanhf(val);
    }
}

// gather 8H features and split to bf16 hi/lo
__global__ void gather_feats_kernel(const float* __restrict__ pv,
                                    const float* __restrict__ tv,
                                    const int* __restrict__ tpi,
                                    __nv_bfloat16* __restrict__ fhi,
                                    __nv_bfloat16* __restrict__ flo) {
    const int s = blockIdx.x;
    const int i0 = tpi[s * 3 + 0];
    const int i1 = tpi[s * 3 + 1];
    const int i2 = tpi[s * 3 + 2];
    for (int j = threadIdx.x; j < 2048; j += blockDim.x) {
        int q = j >> 9, c = j & 511;
        float v;
        if (q == 0)      v = pv[((size_t)2 * CC + i0) * D2H + c];
        else if (q == 1) v = pv[((size_t)1 * CC + i1) * D2H + c];
        else if (q == 2) v = pv[(size_t)i2 * D2H + c];
        else             v = tv[(size_t)s * D2H + c];
        __nv_bfloat16 h, l; splitbf(v, h, l);
        fhi[(size_t)s * 2048 + j] = h;
        flo[(size_t)s * 2048 + j] = l;
    }
}

__global__ __launch_bounds__(256)
void triple_logit_kernel(const float* __restrict__ fin,
                         const float* __restrict__ tW,
                         const float* __restrict__ tb,
                         float* __restrict__ out) {
    const int s = blockIdx.x;
    float partial = 0.0f;
    #pragma unroll
    for (int it = 0; it < 2; ++it) {
        int c = threadIdx.x + it * 256;
        float v = fin[(size_t)s * D2H + c];
        v = v > 0.0f ? v : 0.0f;
        partial += v * tW[c];
    }
    float tot = blockReduceSum256(partial);
    if (threadIdx.x == 0) out[s] = tot + tb[0];
}

// ---------------------------------------------------------------------------
// Launcher
// ---------------------------------------------------------------------------
extern "C" void kernel_launch(void* const* d_in, const int* in_sizes, int n_in,
                              void* d_out, int out_size) {
    const float* x        = (const float*)d_in[0];
    const float* wih_f    = (const float*)d_in[1];
    const float* whh_f    = (const float*)d_in[2];
    const float* b_f      = (const float*)d_in[3];
    const float* wih_b    = (const float*)d_in[4];
    const float* whh_b    = (const float*)d_in[5];
    const float* b_b      = (const float*)d_in[6];
    const float* pair_hW  = (const float*)d_in[7];
    const float* pair_hb  = (const float*)d_in[8];
    const float* pair_oW  = (const float*)d_in[9];
    const float* pair_ob  = (const float*)d_in[10];
    const float* pair_bo  = (const float*)d_in[11];
    const float* tri_hW   = (const float*)d_in[12];
    const float* tri_hb   = (const float*)d_in[13];
    const float* tri_bo   = (const float*)d_in[14];
    const float* all_hW   = (const float*)d_in[15];
    const float* all_hb   = (const float*)d_in[16];
    const float* out_tW   = (const float*)d_in[17];
    const float* out_tb   = (const float*)d_in[18];
    const int*   occ1     = (const int*)d_in[19];
    const int*   occ2     = (const int*)d_in[20];
    const int*   seg      = (const int*)d_in[21];
    const int*   tri_o1   = (const int*)d_in[22];
    const int*   tri_o2   = (const int*)d_in[23];
    const int*   tri_o3   = (const int*)d_in[24];
    const int*   tri_seg  = (const int*)d_in[25];
    const int*   tri_pi   = (const int*)d_in[26];
    float* out = (float*)d_out;

    float *GxF, *GxB, *flat, *Feat, *cst, *pv, *tv, *fin;
    unsigned *pk, *tk;
    __nv_bfloat16 *xHi, *xLo, *wHiF, *wLoF, *wHiB, *wLoB, *flHi, *flLo;
    __nv_bfloat16 *bcHi, *bcLo, *awHi, *awLo, *ftHi, *ftLo;
    cudaGetSymbolAddress((void**)&GxF,  g_GxF);
    cudaGetSymbolAddress((void**)&GxB,  g_GxB);
    cudaGetSymbolAddress((void**)&flat, g_flat);
    cudaGetSymbolAddress((void**)&Feat, g_Feat);
    cudaGetSymbolAddress((void**)&cst,  g_cstate);
    cudaGetSymbolAddress((void**)&pk,   g_pairKeys);
    cudaGetSymbolAddress((void**)&tk,   g_triKeys);
    cudaGetSymbolAddress((void**)&pv,   g_pv);
    cudaGetSymbolAddress((void**)&tv,   g_tv);
    cudaGetSymbolAddress((void**)&fin,  g_final);
    cudaGetSymbolAddress((void**)&xHi,  g_xHi);
    cudaGetSymbolAddress((void**)&xLo,  g_xLo);
    cudaGetSymbolAddress((void**)&wHiF, g_wHiF);
    cudaGetSymbolAddress((void**)&wLoF, g_wLoF);
    cudaGetSymbolAddress((void**)&wHiB, g_wHiB);
    cudaGetSymbolAddress((void**)&wLoB, g_wLoB);
    cudaGetSymbolAddress((void**)&flHi, g_flatHi);
    cudaGetSymbolAddress((void**)&flLo, g_flatLo);
    cudaGetSymbolAddress((void**)&bcHi, g_BcHi);
    cudaGetSymbolAddress((void**)&bcLo, g_BcLo);
    cudaGetSymbolAddress((void**)&awHi, g_aWHi);
    cudaGetSymbolAddress((void**)&awLo, g_aWLo);
    cudaGetSymbolAddress((void**)&ftHi, g_ftHi);
    cudaGetSymbolAddress((void**)&ftLo, g_ftLo);

    cudaFuncSetAttribute(gemm_bf16x3_kernel,
                         cudaFuncAttributeMaxDynamicSharedMemorySize, SMEM_GEMM);

    // 1) split/pack operands to bf16 hi/lo
    split_pad_kernel<<<4096, 256>>>(x, xHi, xLo, NPOS, EE, EP);
    split_pad_kernel<<<512, 256>>>(wih_f, wHiF, wLoF, G4, EE, EP);
    split_pad_kernel<<<512, 256>>>(wih_b, wHiB, wLoB, G4, EE, EP);
    pack_bcatT_kernel<<<2304, 256>>>(pair_hW, tri_hW, bcHi, bcLo);
    pack_allWT_kernel<<<1024, 256>>>(all_hW, awHi, awLo);

    // 2) input projections: Gx = x @ wih^T + b   (N=1024 -> 4 col tiles)
    gemm_bf16x3_kernel<<<dim3(4, 512), 512, SMEM_GEMM>>>(xHi, xLo, wHiF, wLoF, b_f, GxF, EP);
    gemm_bf16x3_kernel<<<dim3(4, 512), 512, SMEM_GEMM>>>(xHi, xLo, wHiB, wLoB, b_b, GxB, EP);

    // 3) zero segment-max keys
    zero_keys_kernel<<<32768, 256>>>(pk, tk);

    // 4) BiLSTM recurrence (256 fused steps, bf16 split fused in epilogue)
    for (int s = 0; s < TT; ++s)
        lstm_step_kernel<<<dim3(PP / 32, HH / 32, 2), 256>>>(
            GxF, GxB, whh_f, whh_b, flat, flHi, flLo, cst, s);

    // 5) dense feature transform: Feat = flat @ BcatT^T  (N=4608 -> 18 tiles)
    gemm_bf16x3_kernel<<<dim3(NC / 256, NPOS / 128), 512, SMEM_GEMM>>>(
        flHi, flLo, bcHi, bcLo, nullptr, Feat, D2H);

    // 6) segment max pooling
    pair_scatter_kernel<<<3 * MM, 512>>>(Feat, occ1, occ2, seg, pk);
    tri_scatter_kernel<<<MM, 512>>>(Feat, tri_o1, tri_o2, tri_o3, tri_seg, tk);

    // 7) finalize pooled vectors (+ pair logits)
    pair_final_kernel<<<3 * CC, 256>>>(pk, pair_hb, pair_bo, pair_oW, pair_ob, pv, out);
    tri_final_kernel<<<CC, 256>>>(tk, tri_hb, tri_bo, tv);

    // 8) final MLP + triple logits   (N=512 -> 2 col tiles)
    gather_feats_kernel<<<CC, 256>>>(pv, tv, tri_pi, ftHi, ftLo);
    gemm_bf16x3_kernel<<<dim3(D2H / 256, CC / 128), 512, SMEM_GEMM>>>(
        ftHi, ftLo, awHi, awLo, all_hb, fin, 2048);
    triple_logit_kernel<<<CC, 256>>>(fin, out_tW, out_tb, out);
}